// round 7
// baseline (speedup 1.0000x reference)
#include <cuda_runtime.h>
#include <cstdint>
#include <cstddef>

#define BROWS   8192
#define DIN     2048
#define DSTATE  2048
#define NSEG    4

#define BM 128
#define BN 32          // state-cols per block (x4 segments concurrently)
#define BK 16
#define NK (DIN / BK)  // 128
#define SROW 24        // smem row stride in floats (16 data + 8 pad; LDS.64 conflict-free)
#define NSTAGE 4
#define STG_FLOATS (256 * SROW)              // 6144 floats = 24KB per stage
#define SMEM_FLOATS (NSTAGE * STG_FLOATS)    // 24576 floats = 96KB

__device__ float g_gates[BROWS * NSEG];
__device__ __align__(16) float g_xr[BROWS * DIN];           // 64 MB, tf32-rounded x
__device__ __align__(16) float g_wr[NSEG * DSTATE * DIN];   // 64 MB, tf32-rounded W

// ---------------------------------------------------------------------------
// Helpers
// ---------------------------------------------------------------------------
__device__ __forceinline__ float rna_tf32(float f) {
    uint32_t u;
    asm("cvt.rna.tf32.f32 %0, %1;" : "=r"(u) : "f"(f));
    return __uint_as_float(u);
}

#define MMA_TF32(c, a0, a1, a2, a3, b0, b1)                                     \
    asm volatile(                                                               \
        "mma.sync.aligned.m16n8k8.row.col.f32.tf32.tf32.f32 "                   \
        "{%0,%1,%2,%3}, {%4,%5,%6,%7}, {%8,%9}, {%0,%1,%2,%3};"                 \
        : "+f"(c[0]), "+f"(c[1]), "+f"(c[2]), "+f"(c[3])                        \
        : "r"(a0), "r"(a1), "r"(a2), "r"(a3), "r"(b0), "r"(b1))

__device__ __forceinline__ void cp_async16(uint32_t saddr, const float* g) {
    asm volatile("cp.async.cg.shared.global [%0], [%1], 16;" ::"r"(saddr),
                 "l"(g) : "memory");
}
#define CP_COMMIT()  asm volatile("cp.async.commit_group;" ::: "memory")
#define CP_WAIT2()   asm volatile("cp.async.wait_group 2;" ::: "memory")

// ---------------------------------------------------------------------------
// Pre-round kernel: out[i] = round_to_tf32(in[i]) (rna). Vectorized.
// ---------------------------------------------------------------------------
__global__ __launch_bounds__(256) void preround_kernel(const float* __restrict__ in,
                                                       float* __restrict__ out,
                                                       int n4) {
    int i = blockIdx.x * blockDim.x + threadIdx.x;
    int stride = gridDim.x * blockDim.x;
    for (; i < n4; i += stride) {
        float4 v = ((const float4*)in)[i];
        v.x = rna_tf32(v.x); v.y = rna_tf32(v.y);
        v.z = rna_tf32(v.z); v.w = rna_tf32(v.w);
        ((float4*)out)[i] = v;
    }
}

// ---------------------------------------------------------------------------
// Gate kernel: gates[b,s] = sigmoid(x[b,:] . W_gate[s,:] + b_gate[s])
// ---------------------------------------------------------------------------
__global__ __launch_bounds__(256) void gate_kernel(const float* __restrict__ x,
                                                   const float* __restrict__ Wg,
                                                   const float* __restrict__ bg) {
    int warp = threadIdx.x >> 5;
    int lane = threadIdx.x & 31;
    int b = blockIdx.x * 8 + warp;
    const float* xr = x + (size_t)b * DIN;

    float a0 = 0.f, a1 = 0.f, a2 = 0.f, a3 = 0.f;
    for (int i = lane * 4; i < DIN; i += 128) {
        float4 xv = *(const float4*)(xr + i);
        float4 w0 = *(const float4*)(Wg + 0 * DIN + i);
        float4 w1 = *(const float4*)(Wg + 1 * DIN + i);
        float4 w2 = *(const float4*)(Wg + 2 * DIN + i);
        float4 w3 = *(const float4*)(Wg + 3 * DIN + i);
        a0 += xv.x * w0.x + xv.y * w0.y + xv.z * w0.z + xv.w * w0.w;
        a1 += xv.x * w1.x + xv.y * w1.y + xv.z * w1.z + xv.w * w1.w;
        a2 += xv.x * w2.x + xv.y * w2.y + xv.z * w2.z + xv.w * w2.w;
        a3 += xv.x * w3.x + xv.y * w3.y + xv.z * w3.z + xv.w * w3.w;
    }
#pragma unroll
    for (int off = 16; off; off >>= 1) {
        a0 += __shfl_xor_sync(0xFFFFFFFFu, a0, off);
        a1 += __shfl_xor_sync(0xFFFFFFFFu, a1, off);
        a2 += __shfl_xor_sync(0xFFFFFFFFu, a2, off);
        a3 += __shfl_xor_sync(0xFFFFFFFFu, a3, off);
    }
    if (lane == 0) {
        g_gates[b * 4 + 0] = 1.f / (1.f + __expf(-(a0 + bg[0])));
        g_gates[b * 4 + 1] = 1.f / (1.f + __expf(-(a1 + bg[1])));
        g_gates[b * 4 + 2] = 1.f / (1.f + __expf(-(a2 + bg[2])));
        g_gates[b * 4 + 3] = 1.f / (1.f + __expf(-(a3 + bg[3])));
    }
}

// ---------------------------------------------------------------------------
// Fused segment-GEMM + epilogue kernel.
// Block tile: 128 (batch rows) x 32 (state cols) x 4 segments.
// 256 threads = 8 warps as 4 (m) x 2 (n); warp tile 32 x 16 per segment.
// k-column permutation (hw col qb <-> phys 2qb, qb+4 <-> 2qb+1) applied
// identically to A and B makes every fragment pair one LDS.64.
// ---------------------------------------------------------------------------
__global__ __launch_bounds__(256, 2) void dendritic_kernel(
    const float* __restrict__ b_seg,  // (4, 2048)
    const float* __restrict__ th,     // (4, 2048)
    float* __restrict__ out)          // (8192, 2048)
{
    extern __shared__ float smf[];

    const int tid = threadIdx.x;
    const int bm = blockIdx.x;  // batch tile (fast dim -> W slice stays hot in L2)
    const int bn = blockIdx.y;  // state tile

    const int warpId = tid >> 5;
    const int lane = tid & 31;
    const int wm = warpId & 3;   // m offset = wm*32
    const int wn = warpId >> 2;  // n offset = wn*16
    const int g = lane >> 2;     // row within 8
    const int qb = lane & 3;     // k quad

    const uint32_t sm_base = (uint32_t)__cvta_generic_to_shared(smf);

    // ---- fill assignments: 1024 float4 chunks per stage (512 x + 512 w) ----
    const float* gp[4];
    uint32_t sa[4];  // smem byte addr within stage 0
#pragma unroll
    for (int j = 0; j < 4; j++) {
        int chunk = tid + 256 * j;
        int row = chunk >> 2;        // 0..255 (x rows 0..127, w rows 128..255)
        int cc = (chunk & 3) * 4;    // float col 0,4,8,12
        if (row < 128) {
            gp[j] = g_xr + (size_t)(bm * BM + row) * DIN + cc;
        } else {
            int n = row - 128;
            int s = n >> 5;
            int d = bn * BN + (n & 31);
            gp[j] = g_wr + ((size_t)s * DSTATE + d) * DIN + cc;
        }
        sa[j] = sm_base + (uint32_t)(row * SROW + cc) * 4;
    }

    float acc[NSEG][2][2][4];
#pragma unroll
    for (int s = 0; s < NSEG; s++)
#pragma unroll
        for (int mi = 0; mi < 2; mi++)
#pragma unroll
            for (int ni = 0; ni < 2; ni++)
#pragma unroll
                for (int e = 0; e < 4; e++) acc[s][mi][ni][e] = 0.f;

    // ---- prologue: issue stages 0..2 ----
#pragma unroll
    for (int p = 0; p < 3; p++) {
#pragma unroll
        for (int j = 0; j < 4; j++)
            cp_async16(sa[j] + p * (STG_FLOATS * 4), gp[j] + p * BK);
        CP_COMMIT();
    }

    for (int kt = 0; kt < NK; kt++) {
        const int st = kt & 3;
        CP_WAIT2();
        __syncthreads();  // stage kt visible to all; stage (kt-1) compute done

        if (kt + 3 < NK) {
            const int ns = (kt + 3) & 3;
#pragma unroll
            for (int j = 0; j < 4; j++)
                cp_async16(sa[j] + ns * (STG_FLOATS * 4), gp[j] + (kt + 3) * BK);
            CP_COMMIT();
        }

        const float* sx = smf + st * STG_FLOATS;
        const float* sw = smf + st * STG_FLOATS + 128 * SROW;
#pragma unroll
        for (int k8 = 0; k8 < 2; k8++) {
            // permuted k columns: hw slot (qb, qb+4) <- phys (2qb, 2qb+1)
            const int kc = k8 * 8 + 2 * qb;

            // A fragments: (a0,a2) row r, (a1,a3) row r+8, each one LDS.64
            float2 aLo[2], aHi[2];
#pragma unroll
            for (int mi = 0; mi < 2; mi++) {
                int r = wm * 32 + mi * 16 + g;
                aLo[mi] = *(const float2*)(sx + r * SROW + kc);
                aHi[mi] = *(const float2*)(sx + (r + 8) * SROW + kc);
            }
            // B fragments: (b0,b1) one LDS.64 each
            float2 bv[NSEG][2];
#pragma unroll
            for (int s = 0; s < NSEG; s++) {
#pragma unroll
                for (int ni = 0; ni < 2; ni++) {
                    int dr = s * BN + wn * 16 + ni * 8 + g;
                    bv[s][ni] = *(const float2*)(sw + dr * SROW + kc);
                }
            }
#pragma unroll
            for (int s = 0; s < NSEG; s++) {
#pragma unroll
                for (int ni = 0; ni < 2; ni++) {
                    uint32_t B0 = __float_as_uint(bv[s][ni].x);
                    uint32_t B1 = __float_as_uint(bv[s][ni].y);
#pragma unroll
                    for (int mi = 0; mi < 2; mi++) {
                        MMA_TF32(acc[s][mi][ni],
                                 __float_as_uint(aLo[mi].x), __float_as_uint(aHi[mi].x),
                                 __float_as_uint(aLo[mi].y), __float_as_uint(aHi[mi].y),
                                 B0, B1);
                    }
                }
            }
        }
    }

    // ---- epilogue: bias, plateau, gate, sum + 0.1 * signed geo-mean ----
    const int bbase = bm * BM;
    const int dbase = bn * BN;

#pragma unroll
    for (int mi = 0; mi < 2; mi++) {
#pragma unroll
        for (int hh = 0; hh < 2; hh++) {
            const int rloc = wm * 32 + mi * 16 + g + hh * 8;
            const int brow = bbase + rloc;
            float4 gv = *(const float4*)(&g_gates[brow * 4]);
            float gt[NSEG] = {gv.x, gv.y, gv.z, gv.w};
#pragma unroll
            for (int ni = 0; ni < 2; ni++) {
#pragma unroll
                for (int e = 0; e < 2; e++) {
                    const int d = dbase + wn * 16 + ni * 8 + qb * 2 + e;
                    float sumv = 0.f, prodv = 1.f;
#pragma unroll
                    for (int s = 0; s < NSEG; s++) {
                        float seg = acc[s][mi][ni][hh * 2 + e] + b_seg[s * DSTATE + d];
                        float z = 5.f * (seg - th[s * DSTATE + d]);
                        float p = 1.f / (1.f + __expf(-z));
                        float vv = seg * p * gt[s];
                        sumv += vv;
                        prodv *= vv;
                    }
                    float r4 = sqrtf(sqrtf(fabsf(prodv)));
                    out[(size_t)brow * DSTATE + d] = sumv + 0.1f * copysignf(r4, prodv);
                }
            }
        }
    }
}

// ---------------------------------------------------------------------------
extern "C" void kernel_launch(void* const* d_in, const int* in_sizes, int n_in,
                              void* d_out, int out_size) {
    const float* x      = (const float*)d_in[0];
    const float* W_seg  = (const float*)d_in[1];
    const float* b_seg  = (const float*)d_in[2];
    const float* thresh = (const float*)d_in[3];
    const float* W_gate = (const float*)d_in[4];
    const float* b_gate = (const float*)d_in[5];
    float* out = (float*)d_out;
    (void)in_sizes; (void)n_in; (void)out_size;

    float* gx;
    float* gw;
    cudaGetSymbolAddress((void**)&gx, g_xr);
    cudaGetSymbolAddress((void**)&gw, g_wr);

    cudaFuncSetAttribute(dendritic_kernel,
                         cudaFuncAttributeMaxDynamicSharedMemorySize,
                         SMEM_FLOATS * sizeof(float));

    preround_kernel<<<1184, 256>>>(x, gx, BROWS * DIN / 4);
    preround_kernel<<<1184, 256>>>(W_seg, gw, NSEG * DSTATE * DIN / 4);
    gate_kernel<<<BROWS / 8, 256>>>(x, W_gate, b_gate);

    dim3 grid(BROWS / BM, DSTATE / BN);  // (64, 64), bm fast
    dendritic_kernel<<<grid, 256, SMEM_FLOATS * sizeof(float)>>>(
        b_seg, thresh, out);
}

// round 10
// speedup vs baseline: 1.1502x; 1.1502x over previous
#include <cuda_runtime.h>
#include <cstdint>
#include <cstddef>

#define BROWS   8192
#define DIN     2048
#define DSTATE  2048
#define NSEG    4

#define BM 128
#define BN 32          // state-cols per block (x4 segments concurrently)
#define BK 32          // K floats per stage (4 k8 steps per barrier)
#define NK (DIN / BK)  // 64
#define SROW 36        // smem row stride in floats (32 data + 4 pad)
#define NSTAGE 3
#define STG_FLOATS (256 * SROW)              // 9216 floats = 36KB per stage
#define SMEM_FLOATS (NSTAGE * STG_FLOATS)    // 27648 floats = 108KB

__device__ float g_gates[BROWS * NSEG];
__device__ __align__(16) float g_xr[BROWS * DIN];           // 64 MB, tf32-rounded x
__device__ __align__(16) float g_wr[NSEG * DSTATE * DIN];   // 64 MB, tf32-rounded W

// ---------------------------------------------------------------------------
// Helpers
// ---------------------------------------------------------------------------
__device__ __forceinline__ float rna_tf32(float f) {
    uint32_t u;
    asm("cvt.rna.tf32.f32 %0, %1;" : "=r"(u) : "f"(f));
    return __uint_as_float(u);
}

#define MMA_TF32(c, a, b0, b1)                                                  \
    asm volatile(                                                               \
        "mma.sync.aligned.m16n8k8.row.col.f32.tf32.tf32.f32 "                   \
        "{%0,%1,%2,%3}, {%4,%5,%6,%7}, {%8,%9}, {%0,%1,%2,%3};"                 \
        : "+f"(c[0]), "+f"(c[1]), "+f"(c[2]), "+f"(c[3])                        \
        : "r"(a[0]), "r"(a[1]), "r"(a[2]), "r"(a[3]), "r"(b0), "r"(b1))

__device__ __forceinline__ void cp_async16(uint32_t saddr, const float* g) {
    asm volatile("cp.async.cg.shared.global [%0], [%1], 16;" ::"r"(saddr),
                 "l"(g) : "memory");
}
#define CP_COMMIT()  asm volatile("cp.async.commit_group;" ::: "memory")
#define CP_WAIT1()   asm volatile("cp.async.wait_group 1;" ::: "memory")

// ---------------------------------------------------------------------------
// Pre-round kernel: out[i] = round_to_tf32(in[i]) (rna). Vectorized.
// ---------------------------------------------------------------------------
__global__ __launch_bounds__(256) void preround_kernel(const float* __restrict__ in,
                                                       float* __restrict__ out,
                                                       int n4) {
    int i = blockIdx.x * blockDim.x + threadIdx.x;
    int stride = gridDim.x * blockDim.x;
    for (; i < n4; i += stride) {
        float4 v = ((const float4*)in)[i];
        v.x = rna_tf32(v.x); v.y = rna_tf32(v.y);
        v.z = rna_tf32(v.z); v.w = rna_tf32(v.w);
        ((float4*)out)[i] = v;
    }
}

// ---------------------------------------------------------------------------
// Gate kernel: gates[b,s] = sigmoid(x[b,:] . W_gate[s,:] + b_gate[s])
// ---------------------------------------------------------------------------
__global__ __launch_bounds__(256) void gate_kernel(const float* __restrict__ x,
                                                   const float* __restrict__ Wg,
                                                   const float* __restrict__ bg) {
    int warp = threadIdx.x >> 5;
    int lane = threadIdx.x & 31;
    int b = blockIdx.x * 8 + warp;
    const float* xr = x + (size_t)b * DIN;

    float a0 = 0.f, a1 = 0.f, a2 = 0.f, a3 = 0.f;
    for (int i = lane * 4; i < DIN; i += 128) {
        float4 xv = *(const float4*)(xr + i);
        float4 w0 = *(const float4*)(Wg + 0 * DIN + i);
        float4 w1 = *(const float4*)(Wg + 1 * DIN + i);
        float4 w2 = *(const float4*)(Wg + 2 * DIN + i);
        float4 w3 = *(const float4*)(Wg + 3 * DIN + i);
        a0 += xv.x * w0.x + xv.y * w0.y + xv.z * w0.z + xv.w * w0.w;
        a1 += xv.x * w1.x + xv.y * w1.y + xv.z * w1.z + xv.w * w1.w;
        a2 += xv.x * w2.x + xv.y * w2.y + xv.z * w2.z + xv.w * w2.w;
        a3 += xv.x * w3.x + xv.y * w3.y + xv.z * w3.z + xv.w * w3.w;
    }
#pragma unroll
    for (int off = 16; off; off >>= 1) {
        a0 += __shfl_xor_sync(0xFFFFFFFFu, a0, off);
        a1 += __shfl_xor_sync(0xFFFFFFFFu, a1, off);
        a2 += __shfl_xor_sync(0xFFFFFFFFu, a2, off);
        a3 += __shfl_xor_sync(0xFFFFFFFFu, a3, off);
    }
    if (lane == 0) {
        g_gates[b * 4 + 0] = 1.f / (1.f + __expf(-(a0 + bg[0])));
        g_gates[b * 4 + 1] = 1.f / (1.f + __expf(-(a1 + bg[1])));
        g_gates[b * 4 + 2] = 1.f / (1.f + __expf(-(a2 + bg[2])));
        g_gates[b * 4 + 3] = 1.f / (1.f + __expf(-(a3 + bg[3])));
    }
}

// ---------------------------------------------------------------------------
// Fused segment-GEMM + epilogue kernel.
// Block tile: 128 (batch rows) x 32 (state cols) x 4 segments.
// 256 threads = 8 warps as 4 (m) x 2 (n); warp tile 32 x 16 per segment.
// BK=32 (4 k8 steps) per barrier -> 64 barriers total. 3-stage cp.async ring.
// ---------------------------------------------------------------------------
__global__ __launch_bounds__(256, 2) void dendritic_kernel(
    const float* __restrict__ b_seg,  // (4, 2048)
    const float* __restrict__ th,     // (4, 2048)
    float* __restrict__ out)          // (8192, 2048)
{
    extern __shared__ float smf[];

    const int tid = threadIdx.x;
    const int bm = blockIdx.x;  // batch tile (fast dim -> W slice stays hot in L2)
    const int bn = blockIdx.y;  // state tile

    const int warpId = tid >> 5;
    const int lane = tid & 31;
    const int wm = warpId & 3;   // m offset = wm*32
    const int wn = warpId >> 2;  // n offset = wn*16
    const int g = lane >> 2;     // row within 8
    const int qb = lane & 3;     // k quad

    const uint32_t sm_base = (uint32_t)__cvta_generic_to_shared(smf);

    // ---- fill assignments: 2048 float4 chunks per stage, 8 per thread ----
    // chunk c = tid + 256*j: row = (tid>>3) + 32*j, col = (tid&7)*4 (constant).
    // j=0..3 -> x rows r0+32j; j=4..7 -> w rows: seg s=j-4, d = bn*32 + r0.
    const int r0 = tid >> 3;
    const int col = (tid & 7) * 4;
    const float* gx0 = g_xr + (size_t)(bm * BM + r0) * DIN + col;
    const float* gw0 = g_wr + ((size_t)bn * BN + r0) * DIN + col;
    const uint32_t sa_x = sm_base + (uint32_t)(r0 * SROW + col) * 4;
    const uint32_t sa_w = sm_base + (uint32_t)((128 + r0) * SROW + col) * 4;

    float acc[NSEG][2][2][4];
#pragma unroll
    for (int s = 0; s < NSEG; s++)
#pragma unroll
        for (int mi = 0; mi < 2; mi++)
#pragma unroll
            for (int ni = 0; ni < 2; ni++)
#pragma unroll
                for (int e = 0; e < 4; e++) acc[s][mi][ni][e] = 0.f;

    // ---- prologue: issue stages 0,1 ----
#pragma unroll
    for (int p = 0; p < 2; p++) {
        const uint32_t sb = (uint32_t)(p * STG_FLOATS * 4);
#pragma unroll
        for (int j = 0; j < 4; j++)
            cp_async16(sa_x + sb + (uint32_t)(32 * j * SROW) * 4,
                       gx0 + (size_t)(32 * j) * DIN + p * BK);
#pragma unroll
        for (int j = 0; j < 4; j++)
            cp_async16(sa_w + sb + (uint32_t)(32 * j * SROW) * 4,
                       gw0 + (size_t)j * DSTATE * DIN + p * BK);
        CP_COMMIT();
    }

    int st = 0;
    for (int kt = 0; kt < NK; kt++) {
        CP_WAIT1();
        __syncthreads();  // stage kt visible; stage (kt-1) compute done

        if (kt + 2 < NK) {
            const int ns = (st + 2 >= NSTAGE) ? st + 2 - NSTAGE : st + 2;
            const uint32_t sb = (uint32_t)(ns * STG_FLOATS * 4);
#pragma unroll
            for (int j = 0; j < 4; j++)
                cp_async16(sa_x + sb + (uint32_t)(32 * j * SROW) * 4,
                           gx0 + (size_t)(32 * j) * DIN + (kt + 2) * BK);
#pragma unroll
            for (int j = 0; j < 4; j++)
                cp_async16(sa_w + sb + (uint32_t)(32 * j * SROW) * 4,
                           gw0 + (size_t)j * DSTATE * DIN + (kt + 2) * BK);
        }
        CP_COMMIT();  // uniform one group per kt (may be empty near the tail)

        const float* sx = smf + st * STG_FLOATS;
        const float* sw = smf + st * STG_FLOATS + 128 * SROW;
#pragma unroll
        for (int k8 = 0; k8 < 4; k8++) {
            const int k0 = k8 * 8;
            uint32_t A[2][4];
#pragma unroll
            for (int mi = 0; mi < 2; mi++) {
                int r = wm * 32 + mi * 16 + g;
                A[mi][0] = __float_as_uint(sx[r * SROW + k0 + qb]);
                A[mi][1] = __float_as_uint(sx[(r + 8) * SROW + k0 + qb]);
                A[mi][2] = __float_as_uint(sx[r * SROW + k0 + qb + 4]);
                A[mi][3] = __float_as_uint(sx[(r + 8) * SROW + k0 + qb + 4]);
            }
#pragma unroll
            for (int s = 0; s < NSEG; s++) {
#pragma unroll
                for (int ni = 0; ni < 2; ni++) {
                    int dr = s * BN + wn * 16 + ni * 8 + g;
                    uint32_t B0 = __float_as_uint(sw[dr * SROW + k0 + qb]);
                    uint32_t B1 = __float_as_uint(sw[dr * SROW + k0 + qb + 4]);
#pragma unroll
                    for (int mi = 0; mi < 2; mi++) {
                        MMA_TF32(acc[s][mi][ni], A[mi], B0, B1);
                    }
                }
            }
        }

        st = (st + 1 >= NSTAGE) ? 0 : st + 1;
    }

    // ---- epilogue: bias, plateau, gate, sum + 0.1 * signed geo-mean ----
    const int bbase = bm * BM;
    const int dbase = bn * BN;

#pragma unroll
    for (int mi = 0; mi < 2; mi++) {
#pragma unroll
        for (int hh = 0; hh < 2; hh++) {
            const int rloc = wm * 32 + mi * 16 + g + hh * 8;
            const int brow = bbase + rloc;
            float4 gv = *(const float4*)(&g_gates[brow * 4]);
            float gt[NSEG] = {gv.x, gv.y, gv.z, gv.w};
#pragma unroll
            for (int ni = 0; ni < 2; ni++) {
#pragma unroll
                for (int e = 0; e < 2; e++) {
                    const int d = dbase + wn * 16 + ni * 8 + qb * 2 + e;
                    float sumv = 0.f, prodv = 1.f;
#pragma unroll
                    for (int s = 0; s < NSEG; s++) {
                        float seg = acc[s][mi][ni][hh * 2 + e] + b_seg[s * DSTATE + d];
                        float z = 5.f * (seg - th[s * DSTATE + d]);
                        float p = 1.f / (1.f + __expf(-z));
                        float vv = seg * p * gt[s];
                        sumv += vv;
                        prodv *= vv;
                    }
                    float r4 = sqrtf(sqrtf(fabsf(prodv)));
                    out[(size_t)brow * DSTATE + d] = sumv + 0.1f * copysignf(r4, prodv);
                }
            }
        }
    }
}

// ---------------------------------------------------------------------------
extern "C" void kernel_launch(void* const* d_in, const int* in_sizes, int n_in,
                              void* d_out, int out_size) {
    const float* x      = (const float*)d_in[0];
    const float* W_seg  = (const float*)d_in[1];
    const float* b_seg  = (const float*)d_in[2];
    const float* thresh = (const float*)d_in[3];
    const float* W_gate = (const float*)d_in[4];
    const float* b_gate = (const float*)d_in[5];
    float* out = (float*)d_out;
    (void)in_sizes; (void)n_in; (void)out_size;

    float* gx;
    float* gw;
    cudaGetSymbolAddress((void**)&gx, g_xr);
    cudaGetSymbolAddress((void**)&gw, g_wr);

    cudaFuncSetAttribute(dendritic_kernel,
                         cudaFuncAttributeMaxDynamicSharedMemorySize,
                         SMEM_FLOATS * sizeof(float));

    preround_kernel<<<1184, 256>>>(x, gx, BROWS * DIN / 4);
    preround_kernel<<<1184, 256>>>(W_seg, gw, NSEG * DSTATE * DIN / 4);
    gate_kernel<<<BROWS / 8, 256>>>(x, W_gate, b_gate);

    dim3 grid(BROWS / BM, DSTATE / BN);  // (64, 64), bm fast
    dendritic_kernel<<<grid, 256, SMEM_FLOATS * sizeof(float)>>>(
        b_seg, thresh, out);
}